// round 2
// baseline (speedup 1.0000x reference)
#include <cuda_runtime.h>

// ChannelPruner: out[b,o,h,w] = sum_c w[o,c] * x[b,c,h,w]
// x: (32, 256, 56, 56) fp32, w: (256, 256, 1, 1) fp32 (very sparse in practice).
// Strategy: runtime-compact W's nonzeros (general correctness), then a
// streaming gather-accumulate kernel that touches x only for nonzero coeffs.

#define N_C 256
#define HW  3136           // 56*56
#define HW4 784            // HW / 4 (float4 granularity)
#define N_B 32

// Scratch: device globals (no allocation allowed in kernel_launch).
__device__ int   g_nnz[N_C];
__device__ int   g_cidx[N_C * N_C];
__device__ float g_cval[N_C * N_C];

// Kernel A: compact each row of W into (col, val) pairs. One warp per row.
__global__ void __launch_bounds__(32) compact_w(const float* __restrict__ w) {
    const int o    = blockIdx.x;
    const int lane = threadIdx.x;
    const float* row = w + o * N_C;

    int base = 0;
#pragma unroll
    for (int k = 0; k < N_C / 32; ++k) {
        const int   c = k * 32 + lane;
        const float v = row[c];
        const unsigned mask = __ballot_sync(0xFFFFFFFFu, v != 0.0f);
        if (v != 0.0f) {
            const int pos = base + __popc(mask & ((1u << lane) - 1u));
            g_cidx[o * N_C + pos] = c;
            g_cval[o * N_C + pos] = v;
        }
        base += __popc(mask);
    }
    if (lane == 0) g_nnz[o] = base;
}

// Kernel B: one block per (b, o). Stream 784 float4 of the (h,w) plane,
// accumulating over the nonzero coefficients of row o (cached in smem).
__global__ void __launch_bounds__(256) sparse_apply(const float4* __restrict__ x,
                                                    float4* __restrict__ out) {
    const int bo = blockIdx.x;          // b * 256 + o
    const int o  = bo & (N_C - 1);
    const int b  = bo >> 8;

    __shared__ int   s_nnz;
    __shared__ int   s_idx[N_C];
    __shared__ float s_val[N_C];

    const int tid = threadIdx.x;
    if (tid == 0) s_nnz = g_nnz[o];
    __syncthreads();
    const int nnz = s_nnz;
    if (tid < nnz) {
        s_idx[tid] = g_cidx[o * N_C + tid];
        s_val[tid] = g_cval[o * N_C + tid];
    }
    __syncthreads();

    float4* __restrict__ orow = out + (size_t)bo * HW4;
    const float4* __restrict__ xb = x + (size_t)b * N_C * HW4;

    // 784 / 256 -> 3 full strides + partial; keep it a simple strided loop.
    for (int i = tid; i < HW4; i += 256) {
        float4 acc = make_float4(0.f, 0.f, 0.f, 0.f);
        for (int j = 0; j < nnz; ++j) {
            const int   c = s_idx[j];
            const float v = s_val[j];
            const float4 xv = xb[(size_t)c * HW4 + i];
            acc.x += v * xv.x;
            acc.y += v * xv.y;
            acc.z += v * xv.z;
            acc.w += v * xv.w;
        }
        orow[i] = acc;
    }
}

extern "C" void kernel_launch(void* const* d_in, const int* in_sizes, int n_in,
                              void* d_out, int out_size) {
    const float* x = (const float*)d_in[0];          // (32, 256, 56, 56)
    const float* w = (const float*)d_in[1];          // (256, 256, 1, 1)
    float* out = (float*)d_out;                      // (32, 256, 56, 56)

    compact_w<<<N_C, 32>>>(w);
    sparse_apply<<<N_B * N_C, 256>>>((const float4*)x, (float4*)out);
}

// round 3
// speedup vs baseline: 1.1882x; 1.1882x over previous
#include <cuda_runtime.h>

// ChannelPruner: out[b,o,h,w] = sum_c w[o,c] * x[b,c,h,w]
// x: (32, 256, 56, 56) fp32, w: (256, 256) fp32 (sparse at runtime).
// Single fused kernel: each block owns one (b, o) output plane, compacts
// W's row o in shared memory (order-irrelevant append), then streams the
// plane with 4-way batched float4 loads per nonzero coefficient.

#define N_C 256
#define HW4 784            // 56*56 / 4 (float4 per plane)
#define N_B 32

__global__ void __launch_bounds__(256) pruner_fused(const float4* __restrict__ x,
                                                    const float*  __restrict__ w,
                                                    float4* __restrict__ out) {
    const int bo = blockIdx.x;          // b * 256 + o
    const int o  = bo & (N_C - 1);
    const int b  = bo >> 8;
    const int tid = threadIdx.x;

    __shared__ int   s_cnt;
    __shared__ int   s_idx[N_C];
    __shared__ float s_val[N_C];

    if (tid == 0) s_cnt = 0;
    __syncthreads();

    // Compact row o of W. Order doesn't matter (summation is commutative).
    {
        const float v = __ldg(w + o * N_C + tid);
        if (v != 0.0f) {
            const int pos = atomicAdd(&s_cnt, 1);
            s_idx[pos] = tid;
            s_val[pos] = v;
        }
    }
    __syncthreads();
    const int nnz = s_cnt;

    const float4* __restrict__ xb   = x   + (size_t)b  * N_C * HW4;
    float4*       __restrict__ orow = out + (size_t)bo * HW4;

    // Each thread owns positions tid, tid+256, tid+512, (tid+768 if tid<16).
    const bool has3 = (tid < HW4 - 768);   // 16 threads carry the tail

    float4 a0 = make_float4(0.f, 0.f, 0.f, 0.f);
    float4 a1 = a0, a2 = a0, a3 = a0;

    for (int j = 0; j < nnz; ++j) {
        const float4* __restrict__ p = xb + (size_t)s_idx[j] * HW4 + tid;
        const float v = s_val[j];
        // Batch all independent loads before consuming (MLP = 4).
        const float4 v0 = __ldcs(p);
        const float4 v1 = __ldcs(p + 256);
        const float4 v2 = __ldcs(p + 512);
        float4 v3;
        if (has3) v3 = __ldcs(p + 768);
        a0.x += v * v0.x; a0.y += v * v0.y; a0.z += v * v0.z; a0.w += v * v0.w;
        a1.x += v * v1.x; a1.y += v * v1.y; a1.z += v * v1.z; a1.w += v * v1.w;
        a2.x += v * v2.x; a2.y += v * v2.y; a2.z += v * v2.z; a2.w += v * v2.w;
        if (has3) {
            a3.x += v * v3.x; a3.y += v * v3.y; a3.z += v * v3.z; a3.w += v * v3.w;
        }
    }

    __stcs(orow + tid,       a0);
    __stcs(orow + tid + 256, a1);
    __stcs(orow + tid + 512, a2);
    if (has3) __stcs(orow + tid + 768, a3);
}

extern "C" void kernel_launch(void* const* d_in, const int* in_sizes, int n_in,
                              void* d_out, int out_size) {
    const float* x = (const float*)d_in[0];   // (32, 256, 56, 56)
    const float* w = (const float*)d_in[1];   // (256, 256, 1, 1)
    float* out = (float*)d_out;               // (32, 256, 56, 56)

    pruner_fused<<<N_B * N_C, 256>>>((const float4*)x, w, (float4*)out);
}